// round 12
// baseline (speedup 1.0000x reference)
#include <cuda_runtime.h>
#include <cuda_bf16.h>
#include <math.h>

#define N_NODES    500000
#define NUM_GRAPHS 1024

// Scratch (no cudaMalloc allowed). BSS-zeroed at load; self-cleaning per call.
__device__ float g_agg [N_NODES * 4];      // 8 MB, L2-resident
__device__ float g_sums[NUM_GRAPHS * 4];
__device__ float g_cnts[NUM_GRAPHS];

// ---------------------------------------------------------------------------
// Kernel 1: edge scatter  agg[dst] += x[src]   (4 edges/thread, __ldcg)
// Pinned at the LTS random-sector-op ceiling (L2=90%). CLOSED — do not touch.
// ---------------------------------------------------------------------------
__global__ void __launch_bounds__(256) k_edge(const float4* __restrict__ x,
                                              const int*    __restrict__ src,
                                              const int*    __restrict__ dst,
                                              int E) {
    int q  = blockIdx.x * blockDim.x + threadIdx.x;   // quad index
    int Eq = E >> 2;                                   // full quads

    if (q < Eq) {
        int4 s4 = __ldcs(reinterpret_cast<const int4*>(src) + q);
        int4 d4 = __ldcs(reinterpret_cast<const int4*>(dst) + q);

        float4 v0 = __ldcg(x + s4.x);
        float4 v1 = __ldcg(x + s4.y);
        float4 v2 = __ldcg(x + s4.z);
        float4 v3 = __ldcg(x + s4.w);

        asm volatile("red.global.add.v4.f32 [%0], {%1, %2, %3, %4};"
                     :: "l"(&g_agg[(size_t)d4.x * 4]),
                        "f"(v0.x), "f"(v0.y), "f"(v0.z), "f"(v0.w) : "memory");
        asm volatile("red.global.add.v4.f32 [%0], {%1, %2, %3, %4};"
                     :: "l"(&g_agg[(size_t)d4.y * 4]),
                        "f"(v1.x), "f"(v1.y), "f"(v1.z), "f"(v1.w) : "memory");
        asm volatile("red.global.add.v4.f32 [%0], {%1, %2, %3, %4};"
                     :: "l"(&g_agg[(size_t)d4.z * 4]),
                        "f"(v2.x), "f"(v2.y), "f"(v2.z), "f"(v2.w) : "memory");
        asm volatile("red.global.add.v4.f32 [%0], {%1, %2, %3, %4};"
                     :: "l"(&g_agg[(size_t)d4.w * 4]),
                        "f"(v3.x), "f"(v3.y), "f"(v3.z), "f"(v3.w) : "memory");
    } else if (q == Eq) {
        for (int i = Eq * 4; i < E; i++) {
            int s = __ldg(src + i);
            int d = __ldg(dst + i);
            float4 v = __ldcg(x + s);
            asm volatile("red.global.add.v4.f32 [%0], {%1, %2, %3, %4};"
                         :: "l"(&g_agg[(size_t)d * 4]),
                            "f"(v.x), "f"(v.y), "f"(v.z), "f"(v.w) : "memory");
        }
    }
}

// ---------------------------------------------------------------------------
// MLP helper: h(4) -> ReLU(Lin 4->16) -> Lin(16->4) -> ReLU, in registers.
// ---------------------------------------------------------------------------
__device__ __forceinline__ void mlp4(float h0, float h1, float h2, float h3,
                                     const float* __restrict__ sW1,
                                     const float* __restrict__ sb1,
                                     const float* __restrict__ sW2,
                                     const float* __restrict__ sb2,
                                     float o[4]) {
    float a[4];
    #pragma unroll
    for (int k = 0; k < 4; k++) a[k] = sb2[k];
    #pragma unroll
    for (int j = 0; j < 16; j++) {
        float tj = sb1[j]
                 + h0 * sW1[0 * 16 + j]
                 + h1 * sW1[1 * 16 + j]
                 + h2 * sW1[2 * 16 + j]
                 + h3 * sW1[3 * 16 + j];
        tj = fmaxf(tj, 0.0f);
        #pragma unroll
        for (int k = 0; k < 4; k++) a[k] += tj * sW2[j * 4 + k];
    }
    #pragma unroll
    for (int k = 0; k < 4; k++) o[k] = fmaxf(a[k], 0.0f);
}

// ---------------------------------------------------------------------------
// Kernel 2: per-node MLP + pooled sum, TWO nodes per thread (N even).
// Pairs almost always share a graph id -> combine in registers; rare split
// pairs flush the first half directly. Then uniform-warp fast path
// (butterfly) or segmented-scan slow path. Self-cleaning: zeroes g_agg.
// ---------------------------------------------------------------------------
__global__ void __launch_bounds__(256) k_node(const float4* __restrict__ x,
                       const int*    __restrict__ batch,
                       const float*  __restrict__ eps_p,
                       const float*  __restrict__ W1,   // [4,16] row-major
                       const float*  __restrict__ b1,   // [16]
                       const float*  __restrict__ W2,   // [16,4] row-major
                       const float*  __restrict__ b2) { // [4]
    __shared__ float sW1[64], sb1[16], sW2[64], sb2[4];
    __shared__ float seps;
    int t = threadIdx.x;
    if (t < 64)  sW1[t] = W1[t];
    if (t < 16)  sb1[t] = b1[t];
    if (t >= 64 && t < 128) sW2[t - 64] = W2[t - 64];
    if (t >= 128 && t < 132) sb2[t - 128] = b2[t - 128];
    if (t == 132) seps = 1.0f + eps_p[0];
    __syncthreads();

    int p    = blockIdx.x * blockDim.x + threadIdx.x;   // pair index
    int base = p * 2;

    float o0 = 0.f, o1 = 0.f, o2 = 0.f, o3 = 0.f, cnt = 0.f;
    int g = -1;

    if (base < N_NODES) {       // N even => base+1 also valid
        int2 gb2 = __ldg(reinterpret_cast<const int2*>(batch) + p);
        float4 xa = __ldg(x + base);
        float4 xb = __ldg(x + base + 1);
        float4* aggv = reinterpret_cast<float4*>(g_agg);
        float4 aa = aggv[base];
        float4 ab = aggv[base + 1];
        aggv[base]     = make_float4(0.f, 0.f, 0.f, 0.f);  // reset for replay
        aggv[base + 1] = make_float4(0.f, 0.f, 0.f, 0.f);
        float se = seps;

        float oa[4], ob[4];
        mlp4(se * xa.x + aa.x, se * xa.y + aa.y,
             se * xa.z + aa.z, se * xa.w + aa.w, sW1, sb1, sW2, sb2, oa);
        mlp4(se * xb.x + ab.x, se * xb.y + ab.y,
             se * xb.z + ab.z, se * xb.w + ab.w, sW1, sb1, sW2, sb2, ob);

        if (gb2.x == gb2.y) {   // common case: pair in one graph
            g = gb2.x;
            o0 = oa[0] + ob[0]; o1 = oa[1] + ob[1];
            o2 = oa[2] + ob[2]; o3 = oa[3] + ob[3];
            cnt = 2.0f;
        } else {                // rare boundary inside the pair
            atomicAdd(&g_sums[gb2.x * 4 + 0], oa[0]);
            atomicAdd(&g_sums[gb2.x * 4 + 1], oa[1]);
            atomicAdd(&g_sums[gb2.x * 4 + 2], oa[2]);
            atomicAdd(&g_sums[gb2.x * 4 + 3], oa[3]);
            atomicAdd(&g_cnts[gb2.x], 1.0f);
            g = gb2.y;
            o0 = ob[0]; o1 = ob[1]; o2 = ob[2]; o3 = ob[3];
            cnt = 1.0f;
        }
    }

    unsigned lane = threadIdx.x & 31u;
    int g0 = __shfl_sync(0xFFFFFFFFu, g, 0);

    if (__all_sync(0xFFFFFFFFu, g == g0)) {
        // fast path: whole warp (64 nodes) in one graph
        #pragma unroll
        for (int off = 16; off > 0; off >>= 1) {
            o0  += __shfl_xor_sync(0xFFFFFFFFu, o0,  off);
            o1  += __shfl_xor_sync(0xFFFFFFFFu, o1,  off);
            o2  += __shfl_xor_sync(0xFFFFFFFFu, o2,  off);
            o3  += __shfl_xor_sync(0xFFFFFFFFu, o3,  off);
            cnt += __shfl_xor_sync(0xFFFFFFFFu, cnt, off);
        }
        if (lane == 0 && g0 >= 0) {
            atomicAdd(&g_sums[g0 * 4 + 0], o0);
            atomicAdd(&g_sums[g0 * 4 + 1], o1);
            atomicAdd(&g_sums[g0 * 4 + 2], o2);
            atomicAdd(&g_sums[g0 * 4 + 3], o3);
            atomicAdd(&g_cnts[g0], cnt);
        }
    } else {
        // slow path: warp-segmented inclusive scan over sorted suffix ids
        #pragma unroll
        for (int off = 1; off < 32; off <<= 1) {
            int   gg = __shfl_up_sync(0xFFFFFFFFu, g,   off);
            float t0 = __shfl_up_sync(0xFFFFFFFFu, o0,  off);
            float t1 = __shfl_up_sync(0xFFFFFFFFu, o1,  off);
            float t2 = __shfl_up_sync(0xFFFFFFFFu, o2,  off);
            float t3 = __shfl_up_sync(0xFFFFFFFFu, o3,  off);
            float tc = __shfl_up_sync(0xFFFFFFFFu, cnt, off);
            if (lane >= (unsigned)off && gg == g) {
                o0 += t0; o1 += t1; o2 += t2; o3 += t3; cnt += tc;
            }
        }
        int gnext = __shfl_down_sync(0xFFFFFFFFu, g, 1);
        bool last = (lane == 31u) || (gnext != g);
        if (last && g >= 0) {
            atomicAdd(&g_sums[g * 4 + 0], o0);
            atomicAdd(&g_sums[g * 4 + 1], o1);
            atomicAdd(&g_sums[g * 4 + 2], o2);
            atomicAdd(&g_sums[g * 4 + 3], o3);
            atomicAdd(&g_cnts[g], cnt);
        }
    }
}

// ---------------------------------------------------------------------------
// Kernel 3: mean pool + log_softmax; zeroes g_sums/g_cnts after consuming.
// ---------------------------------------------------------------------------
__global__ void k_pool(float* __restrict__ out) {
    int g = blockIdx.x * blockDim.x + threadIdx.x;
    if (g >= NUM_GRAPHS) return;
    float c = fmaxf(g_cnts[g], 1.0f);
    g_cnts[g] = 0.0f;
    float v[4];
    float m = -INFINITY;
    #pragma unroll
    for (int k = 0; k < 4; k++) {
        v[k] = g_sums[g * 4 + k] / c;
        g_sums[g * 4 + k] = 0.0f;
        m = fmaxf(m, v[k]);
    }
    float s = 0.0f;
    #pragma unroll
    for (int k = 0; k < 4; k++) s += expf(v[k] - m);
    float l = m + logf(s);
    #pragma unroll
    for (int k = 0; k < 4; k++) out[g * 4 + k] = v[k] - l;
}

// ---------------------------------------------------------------------------
extern "C" void kernel_launch(void* const* d_in, const int* in_sizes, int n_in,
                              void* d_out, int out_size) {
    const float4* x   = (const float4*)d_in[0];
    const int*    ei  = (const int*)   d_in[1];   // [2, E]
    const int*    bat = (const int*)   d_in[2];
    const float*  eps = (const float*) d_in[3];
    const float*  W1  = (const float*) d_in[4];
    const float*  b1  = (const float*) d_in[5];
    const float*  W2  = (const float*) d_in[6];
    const float*  b2  = (const float*) d_in[7];
    float* out = (float*)d_out;

    int E = in_sizes[1] / 2;
    const int* src = ei;
    const int* dst = ei + E;

    int quads = E / 4 + 1;                    // +1 thread for the tail
    int pairs = (N_NODES + 1) / 2;            // 250000
    k_edge<<<(quads + 255) / 256, 256>>>(x, src, dst, E);
    k_node<<<(pairs + 255) / 256, 256>>>(x, bat, eps, W1, b1, W2, b2);
    k_pool<<<(NUM_GRAPHS + 255) / 256, 256>>>(out);
}

// round 13
// speedup vs baseline: 1.5794x; 1.5794x over previous
#include <cuda_runtime.h>
#include <cuda_bf16.h>
#include <math.h>

#define N_NODES    500000
#define NUM_GRAPHS 1024

// Scratch (no cudaMalloc allowed). BSS-zeroed at load; self-cleaning per call.
__device__ float g_agg [N_NODES * 4];      // 8 MB, L2-resident
__device__ float g_sums[NUM_GRAPHS * 4];
__device__ float g_cnts[NUM_GRAPHS];

// ---------------------------------------------------------------------------
// Kernel 1: edge scatter  agg[dst] += x[src]   (4 edges/thread, __ldcg)
// Pinned at the LTS random-sector-op ceiling (L2=90% on healthy runs).
// CLOSED — byte-identical to the 123us best config.
// ---------------------------------------------------------------------------
__global__ void __launch_bounds__(256) k_edge(const float4* __restrict__ x,
                                              const int*    __restrict__ src,
                                              const int*    __restrict__ dst,
                                              int E) {
    int q  = blockIdx.x * blockDim.x + threadIdx.x;   // quad index
    int Eq = E >> 2;                                   // full quads

    if (q < Eq) {
        int4 s4 = __ldcs(reinterpret_cast<const int4*>(src) + q);
        int4 d4 = __ldcs(reinterpret_cast<const int4*>(dst) + q);

        float4 v0 = __ldcg(x + s4.x);
        float4 v1 = __ldcg(x + s4.y);
        float4 v2 = __ldcg(x + s4.z);
        float4 v3 = __ldcg(x + s4.w);

        asm volatile("red.global.add.v4.f32 [%0], {%1, %2, %3, %4};"
                     :: "l"(&g_agg[(size_t)d4.x * 4]),
                        "f"(v0.x), "f"(v0.y), "f"(v0.z), "f"(v0.w) : "memory");
        asm volatile("red.global.add.v4.f32 [%0], {%1, %2, %3, %4};"
                     :: "l"(&g_agg[(size_t)d4.y * 4]),
                        "f"(v1.x), "f"(v1.y), "f"(v1.z), "f"(v1.w) : "memory");
        asm volatile("red.global.add.v4.f32 [%0], {%1, %2, %3, %4};"
                     :: "l"(&g_agg[(size_t)d4.z * 4]),
                        "f"(v2.x), "f"(v2.y), "f"(v2.z), "f"(v2.w) : "memory");
        asm volatile("red.global.add.v4.f32 [%0], {%1, %2, %3, %4};"
                     :: "l"(&g_agg[(size_t)d4.w * 4]),
                        "f"(v3.x), "f"(v3.y), "f"(v3.z), "f"(v3.w) : "memory");
    } else if (q == Eq) {
        for (int i = Eq * 4; i < E; i++) {
            int s = __ldg(src + i);
            int d = __ldg(dst + i);
            float4 v = __ldcg(x + s);
            asm volatile("red.global.add.v4.f32 [%0], {%1, %2, %3, %4};"
                         :: "l"(&g_agg[(size_t)d * 4]),
                            "f"(v.x), "f"(v.y), "f"(v.z), "f"(v.w) : "memory");
        }
    }
}

// ---------------------------------------------------------------------------
// Kernel 2: per-node MLP + pooled sum (one thread per node — R11 best shape).
// Fast path for graph-uniform warps (~93%): butterfly reduce + 1 flush.
// Slow path (boundary/tail warps): warp-segmented scan.
// Self-cleaning: zeroes g_agg after consuming it.
// ---------------------------------------------------------------------------
__global__ void __launch_bounds__(256) k_node(const float4* __restrict__ x,
                       const int*    __restrict__ batch,
                       const float*  __restrict__ eps_p,
                       const float*  __restrict__ W1,   // [4,16] row-major
                       const float*  __restrict__ b1,   // [16]
                       const float*  __restrict__ W2,   // [16,4] row-major
                       const float*  __restrict__ b2) { // [4]
    __shared__ float sW1[64], sb1[16], sW2[64], sb2[4];
    __shared__ float seps;
    int t = threadIdx.x;
    if (t < 64)  sW1[t] = W1[t];
    if (t < 16)  sb1[t] = b1[t];
    if (t >= 64 && t < 128) sW2[t - 64] = W2[t - 64];
    if (t >= 128 && t < 132) sb2[t - 128] = b2[t - 128];
    if (t == 132) seps = 1.0f + eps_p[0];
    __syncthreads();

    int i = blockIdx.x * blockDim.x + threadIdx.x;

    float o0 = 0.f, o1 = 0.f, o2 = 0.f, o3 = 0.f, cnt = 0.f;
    int g = -1;

    if (i < N_NODES) {
        float4 xv = __ldg(x + i);
        float4* aggv = reinterpret_cast<float4*>(g_agg);
        float4 av = aggv[i];
        aggv[i] = make_float4(0.f, 0.f, 0.f, 0.f);   // reset for next replay
        float se = seps;
        float h0 = se * xv.x + av.x;
        float h1 = se * xv.y + av.y;
        float h2 = se * xv.z + av.z;
        float h3 = se * xv.w + av.w;

        float out4[4];
        #pragma unroll
        for (int k = 0; k < 4; k++) out4[k] = sb2[k];

        #pragma unroll
        for (int j = 0; j < 16; j++) {
            float tj = sb1[j]
                     + h0 * sW1[0 * 16 + j]
                     + h1 * sW1[1 * 16 + j]
                     + h2 * sW1[2 * 16 + j]
                     + h3 * sW1[3 * 16 + j];
            tj = fmaxf(tj, 0.0f);
            #pragma unroll
            for (int k = 0; k < 4; k++) out4[k] += tj * sW2[j * 4 + k];
        }
        o0 = fmaxf(out4[0], 0.0f);
        o1 = fmaxf(out4[1], 0.0f);
        o2 = fmaxf(out4[2], 0.0f);
        o3 = fmaxf(out4[3], 0.0f);
        cnt = 1.0f;
        g = __ldg(batch + i);
    }

    unsigned lane = threadIdx.x & 31u;
    int g0 = __shfl_sync(0xFFFFFFFFu, g, 0);

    if (__all_sync(0xFFFFFFFFu, g == g0)) {
        // fast path: whole warp in one graph
        #pragma unroll
        for (int off = 16; off > 0; off >>= 1) {
            o0  += __shfl_xor_sync(0xFFFFFFFFu, o0,  off);
            o1  += __shfl_xor_sync(0xFFFFFFFFu, o1,  off);
            o2  += __shfl_xor_sync(0xFFFFFFFFu, o2,  off);
            o3  += __shfl_xor_sync(0xFFFFFFFFu, o3,  off);
            cnt += __shfl_xor_sync(0xFFFFFFFFu, cnt, off);
        }
        if (lane == 0 && g0 >= 0) {
            atomicAdd(&g_sums[g0 * 4 + 0], o0);
            atomicAdd(&g_sums[g0 * 4 + 1], o1);
            atomicAdd(&g_sums[g0 * 4 + 2], o2);
            atomicAdd(&g_sums[g0 * 4 + 3], o3);
            atomicAdd(&g_cnts[g0], cnt);
        }
    } else {
        // slow path: warp-segmented inclusive scan over sorted ids
        #pragma unroll
        for (int off = 1; off < 32; off <<= 1) {
            int   gg = __shfl_up_sync(0xFFFFFFFFu, g,   off);
            float t0 = __shfl_up_sync(0xFFFFFFFFu, o0,  off);
            float t1 = __shfl_up_sync(0xFFFFFFFFu, o1,  off);
            float t2 = __shfl_up_sync(0xFFFFFFFFu, o2,  off);
            float t3 = __shfl_up_sync(0xFFFFFFFFu, o3,  off);
            float tc = __shfl_up_sync(0xFFFFFFFFu, cnt, off);
            if (lane >= (unsigned)off && gg == g) {
                o0 += t0; o1 += t1; o2 += t2; o3 += t3; cnt += tc;
            }
        }
        int gnext = __shfl_down_sync(0xFFFFFFFFu, g, 1);
        bool last = (lane == 31u) || (gnext != g);
        if (last && g >= 0) {
            atomicAdd(&g_sums[g * 4 + 0], o0);
            atomicAdd(&g_sums[g * 4 + 1], o1);
            atomicAdd(&g_sums[g * 4 + 2], o2);
            atomicAdd(&g_sums[g * 4 + 3], o3);
            atomicAdd(&g_cnts[g], cnt);
        }
    }
}

// ---------------------------------------------------------------------------
// Kernel 3: mean pool + log_softmax; zeroes g_sums/g_cnts after consuming.
// Fast-math exp/log (well within 1e-3 tolerance).
// ---------------------------------------------------------------------------
__global__ void k_pool(float* __restrict__ out) {
    int g = blockIdx.x * blockDim.x + threadIdx.x;
    if (g >= NUM_GRAPHS) return;
    float c = fmaxf(g_cnts[g], 1.0f);
    g_cnts[g] = 0.0f;
    float rc = 1.0f / c;
    float v[4];
    float m = -INFINITY;
    #pragma unroll
    for (int k = 0; k < 4; k++) {
        v[k] = g_sums[g * 4 + k] * rc;
        g_sums[g * 4 + k] = 0.0f;
        m = fmaxf(m, v[k]);
    }
    float s = 0.0f;
    #pragma unroll
    for (int k = 0; k < 4; k++) s += __expf(v[k] - m);
    float l = m + __logf(s);
    float4 r = make_float4(v[0] - l, v[1] - l, v[2] - l, v[3] - l);
    reinterpret_cast<float4*>(out)[g] = r;
}

// ---------------------------------------------------------------------------
extern "C" void kernel_launch(void* const* d_in, const int* in_sizes, int n_in,
                              void* d_out, int out_size) {
    const float4* x   = (const float4*)d_in[0];
    const int*    ei  = (const int*)   d_in[1];   // [2, E]
    const int*    bat = (const int*)   d_in[2];
    const float*  eps = (const float*) d_in[3];
    const float*  W1  = (const float*) d_in[4];
    const float*  b1  = (const float*) d_in[5];
    const float*  W2  = (const float*) d_in[6];
    const float*  b2  = (const float*) d_in[7];
    float* out = (float*)d_out;

    int E = in_sizes[1] / 2;
    const int* src = ei;
    const int* dst = ei + E;

    int quads = E / 4 + 1;  // +1 thread for the tail
    k_edge<<<(quads + 255) / 256, 256>>>(x, src, dst, E);
    k_node<<<(N_NODES + 255) / 256, 256>>>(x, bat, eps, W1, b1, W2, b2);
    k_pool<<<(NUM_GRAPHS + 255) / 256, 256>>>(out);
}

// round 14
// speedup vs baseline: 1.5801x; 1.0005x over previous
#include <cuda_runtime.h>
#include <cuda_bf16.h>
#include <math.h>

#define N_NODES    500000
#define NUM_GRAPHS 1024

// Scratch (no cudaMalloc allowed). BSS-zeroed at load; self-cleaning per call.
__device__ float g_agg [N_NODES * 4];      // 8 MB, L2-resident
__device__ float g_sums[NUM_GRAPHS * 4];
__device__ float g_cnts[NUM_GRAPHS];

__device__ __forceinline__ void pdl_wait() {
    asm volatile("griddepcontrol.wait;" ::: "memory");
}
__device__ __forceinline__ void pdl_launch_dependents() {
    asm volatile("griddepcontrol.launch_dependents;" ::: "memory");
}

// ---------------------------------------------------------------------------
// Kernel 1: edge scatter  agg[dst] += x[src]   (4 edges/thread, __ldcg)
// Pinned at the LTS random-sector-op ceiling (L2=90%). CLOSED.
// ---------------------------------------------------------------------------
__global__ void __launch_bounds__(256) k_edge(const float4* __restrict__ x,
                                              const int*    __restrict__ src,
                                              const int*    __restrict__ dst,
                                              int E) {
    int q  = blockIdx.x * blockDim.x + threadIdx.x;   // quad index
    int Eq = E >> 2;                                   // full quads

    if (q < Eq) {
        int4 s4 = __ldcs(reinterpret_cast<const int4*>(src) + q);
        int4 d4 = __ldcs(reinterpret_cast<const int4*>(dst) + q);

        float4 v0 = __ldcg(x + s4.x);
        float4 v1 = __ldcg(x + s4.y);
        float4 v2 = __ldcg(x + s4.z);
        float4 v3 = __ldcg(x + s4.w);

        asm volatile("red.global.add.v4.f32 [%0], {%1, %2, %3, %4};"
                     :: "l"(&g_agg[(size_t)d4.x * 4]),
                        "f"(v0.x), "f"(v0.y), "f"(v0.z), "f"(v0.w) : "memory");
        asm volatile("red.global.add.v4.f32 [%0], {%1, %2, %3, %4};"
                     :: "l"(&g_agg[(size_t)d4.y * 4]),
                        "f"(v1.x), "f"(v1.y), "f"(v1.z), "f"(v1.w) : "memory");
        asm volatile("red.global.add.v4.f32 [%0], {%1, %2, %3, %4};"
                     :: "l"(&g_agg[(size_t)d4.z * 4]),
                        "f"(v2.x), "f"(v2.y), "f"(v2.z), "f"(v2.w) : "memory");
        asm volatile("red.global.add.v4.f32 [%0], {%1, %2, %3, %4};"
                     :: "l"(&g_agg[(size_t)d4.w * 4]),
                        "f"(v3.x), "f"(v3.y), "f"(v3.z), "f"(v3.w) : "memory");
    } else if (q == Eq) {
        for (int i = Eq * 4; i < E; i++) {
            int s = __ldg(src + i);
            int d = __ldg(dst + i);
            float4 v = __ldcg(x + s);
            asm volatile("red.global.add.v4.f32 [%0], {%1, %2, %3, %4};"
                         :: "l"(&g_agg[(size_t)d * 4]),
                            "f"(v.x), "f"(v.y), "f"(v.z), "f"(v.w) : "memory");
        }
    }
}

// ---------------------------------------------------------------------------
// Kernel 2: per-node MLP + pooled sum (one thread per node, 512-thr blocks).
// Fast path for graph-uniform warps (~93%): butterfly reduce + 1 flush.
// Slow path: warp-segmented scan. Self-cleaning: zeroes g_agg.
// Signals dependents (k_pool) at the end for PDL.
// ---------------------------------------------------------------------------
__global__ void __launch_bounds__(512) k_node(const float4* __restrict__ x,
                       const int*    __restrict__ batch,
                       const float*  __restrict__ eps_p,
                       const float*  __restrict__ W1,   // [4,16] row-major
                       const float*  __restrict__ b1,   // [16]
                       const float*  __restrict__ W2,   // [16,4] row-major
                       const float*  __restrict__ b2) { // [4]
    __shared__ float sW1[64], sb1[16], sW2[64], sb2[4];
    __shared__ float seps;
    int t = threadIdx.x;
    if (t < 64)  sW1[t] = W1[t];
    if (t < 16)  sb1[t] = b1[t];
    if (t >= 64 && t < 128) sW2[t - 64] = W2[t - 64];
    if (t >= 128 && t < 132) sb2[t - 128] = b2[t - 128];
    if (t == 132) seps = 1.0f + eps_p[0];
    __syncthreads();

    int i = blockIdx.x * blockDim.x + threadIdx.x;

    float o0 = 0.f, o1 = 0.f, o2 = 0.f, o3 = 0.f, cnt = 0.f;
    int g = -1;

    if (i < N_NODES) {
        float4 xv = __ldg(x + i);
        float4* aggv = reinterpret_cast<float4*>(g_agg);
        float4 av = aggv[i];
        aggv[i] = make_float4(0.f, 0.f, 0.f, 0.f);   // reset for next replay
        float se = seps;
        float h0 = se * xv.x + av.x;
        float h1 = se * xv.y + av.y;
        float h2 = se * xv.z + av.z;
        float h3 = se * xv.w + av.w;

        float out4[4];
        #pragma unroll
        for (int k = 0; k < 4; k++) out4[k] = sb2[k];

        #pragma unroll
        for (int j = 0; j < 16; j++) {
            float tj = sb1[j]
                     + h0 * sW1[0 * 16 + j]
                     + h1 * sW1[1 * 16 + j]
                     + h2 * sW1[2 * 16 + j]
                     + h3 * sW1[3 * 16 + j];
            tj = fmaxf(tj, 0.0f);
            #pragma unroll
            for (int k = 0; k < 4; k++) out4[k] += tj * sW2[j * 4 + k];
        }
        o0 = fmaxf(out4[0], 0.0f);
        o1 = fmaxf(out4[1], 0.0f);
        o2 = fmaxf(out4[2], 0.0f);
        o3 = fmaxf(out4[3], 0.0f);
        cnt = 1.0f;
        g = __ldg(batch + i);
    }

    unsigned lane = threadIdx.x & 31u;
    int g0 = __shfl_sync(0xFFFFFFFFu, g, 0);

    if (__all_sync(0xFFFFFFFFu, g == g0)) {
        // fast path: whole warp in one graph
        #pragma unroll
        for (int off = 16; off > 0; off >>= 1) {
            o0  += __shfl_xor_sync(0xFFFFFFFFu, o0,  off);
            o1  += __shfl_xor_sync(0xFFFFFFFFu, o1,  off);
            o2  += __shfl_xor_sync(0xFFFFFFFFu, o2,  off);
            o3  += __shfl_xor_sync(0xFFFFFFFFu, o3,  off);
            cnt += __shfl_xor_sync(0xFFFFFFFFu, cnt, off);
        }
        if (lane == 0 && g0 >= 0) {
            atomicAdd(&g_sums[g0 * 4 + 0], o0);
            atomicAdd(&g_sums[g0 * 4 + 1], o1);
            atomicAdd(&g_sums[g0 * 4 + 2], o2);
            atomicAdd(&g_sums[g0 * 4 + 3], o3);
            atomicAdd(&g_cnts[g0], cnt);
        }
    } else {
        // slow path: warp-segmented inclusive scan over sorted ids
        #pragma unroll
        for (int off = 1; off < 32; off <<= 1) {
            int   gg = __shfl_up_sync(0xFFFFFFFFu, g,   off);
            float t0 = __shfl_up_sync(0xFFFFFFFFu, o0,  off);
            float t1 = __shfl_up_sync(0xFFFFFFFFu, o1,  off);
            float t2 = __shfl_up_sync(0xFFFFFFFFu, o2,  off);
            float t3 = __shfl_up_sync(0xFFFFFFFFu, o3,  off);
            float tc = __shfl_up_sync(0xFFFFFFFFu, cnt, off);
            if (lane >= (unsigned)off && gg == g) {
                o0 += t0; o1 += t1; o2 += t2; o3 += t3; cnt += tc;
            }
        }
        int gnext = __shfl_down_sync(0xFFFFFFFFu, g, 1);
        bool last = (lane == 31u) || (gnext != g);
        if (last && g >= 0) {
            atomicAdd(&g_sums[g * 4 + 0], o0);
            atomicAdd(&g_sums[g * 4 + 1], o1);
            atomicAdd(&g_sums[g * 4 + 2], o2);
            atomicAdd(&g_sums[g * 4 + 3], o3);
            atomicAdd(&g_cnts[g], cnt);
        }
    }

    pdl_launch_dependents();   // let k_pool's 4 blocks spin up
}

// ---------------------------------------------------------------------------
// Kernel 3: mean pool + log_softmax (PDL secondary: waits for k_node's
// completion semantics before reading pools). 4 blocks — negligible
// resource theft while spinning. Zeroes g_sums/g_cnts after consuming.
// ---------------------------------------------------------------------------
__global__ void k_pool(float* __restrict__ out) {
    pdl_wait();                 // all k_node atomics visible after this
    int g = blockIdx.x * blockDim.x + threadIdx.x;
    if (g >= NUM_GRAPHS) return;
    float c = fmaxf(g_cnts[g], 1.0f);
    g_cnts[g] = 0.0f;
    float rc = 1.0f / c;
    float v[4];
    float m = -INFINITY;
    #pragma unroll
    for (int k = 0; k < 4; k++) {
        v[k] = g_sums[g * 4 + k] * rc;
        g_sums[g * 4 + k] = 0.0f;
        m = fmaxf(m, v[k]);
    }
    float s = 0.0f;
    #pragma unroll
    for (int k = 0; k < 4; k++) s += __expf(v[k] - m);
    float l = m + __logf(s);
    float4 r = make_float4(v[0] - l, v[1] - l, v[2] - l, v[3] - l);
    reinterpret_cast<float4*>(out)[g] = r;
}

// ---------------------------------------------------------------------------
extern "C" void kernel_launch(void* const* d_in, const int* in_sizes, int n_in,
                              void* d_out, int out_size) {
    const float4* x   = (const float4*)d_in[0];
    const int*    ei  = (const int*)   d_in[1];   // [2, E]
    const int*    bat = (const int*)   d_in[2];
    const float*  eps = (const float*) d_in[3];
    const float*  W1  = (const float*) d_in[4];
    const float*  b1  = (const float*) d_in[5];
    const float*  W2  = (const float*) d_in[6];
    const float*  b2  = (const float*) d_in[7];
    float* out = (float*)d_out;

    int E = in_sizes[1] / 2;
    const int* src = ei;
    const int* dst = ei + E;

    int quads = E / 4 + 1;  // +1 thread for the tail
    k_edge<<<(quads + 255) / 256, 256>>>(x, src, dst, E);
    k_node<<<(N_NODES + 511) / 512, 512>>>(x, bat, eps, W1, b1, W2, b2);

    // k_pool as PDL secondary of k_node: pre-launches its 4 blocks, which
    // spin at griddepcontrol.wait and fire the instant k_node completes.
    cudaLaunchAttribute pdl[1];
    pdl[0].id = cudaLaunchAttributeProgrammaticStreamSerialization;
    pdl[0].val.programmaticStreamSerializationAllowed = 1;
    cudaLaunchConfig_t cfg = {};
    cfg.gridDim  = dim3((NUM_GRAPHS + 255) / 256);
    cfg.blockDim = dim3(256);
    cfg.attrs    = pdl;
    cfg.numAttrs = 1;
    cudaLaunchKernelEx(&cfg, k_pool, out);
}